// round 16
// baseline (speedup 1.0000x reference)
#include <cuda_runtime.h>
#include <cuda_bf16.h>
#include <mma.h>
#include <cstdint>
#include <math.h>

using namespace nvcuda;

// Problem constants
#define BSn   2
#define Cn    256
#define Hn    200
#define Wn    200
#define HWn   (Hn * Wn)          // 40000
#define Mn    (BSn * HWn)        // 80000
#define MnPad (Mn + 128)         // pad so last-tile overreads stay in bounds
#define NLAYERS 3
#define HDn   32

// -------- scratch (static device arrays; no allocation allowed) ----------
__device__ float g_out [ (size_t)MnPad * Cn ];
__device__ float g_pos [ (size_t)HWn * Cn ];
__device__ float g_val [ (size_t)MnPad * Cn ];
__device__ float g_attn[ (size_t)MnPad * Cn ];
__device__ float g_off [ (size_t)MnPad * 64 ];
__device__ float g_aw  [ (size_t)MnPad * 32 ];

// pre-split bf16 weights: [0]=proj, [1..3]=vp, [4..6]=op, [7..9]=l1, [10..12]=l2
__device__ __nv_bfloat16 g_wb_hi[13][65536];
__device__ __nv_bfloat16 g_wb_lo[13][65536];
__device__ __nv_bfloat16 g_ow_hi[3][96 * 256];
__device__ __nv_bfloat16 g_ow_lo[3][96 * 256];
__device__ float g_obias[3][96];

// -------- streams + events (created at load time, before harness) ---------
static cudaStream_t g_s2, g_s3;
static cudaEvent_t g_evFork, g_evPrep, g_evT1;
static struct StreamInit {
    StreamInit() {
        cudaStreamCreateWithFlags(&g_s2, cudaStreamNonBlocking);
        cudaStreamCreateWithFlags(&g_s3, cudaStreamNonBlocking);
        cudaEventCreateWithFlags(&g_evFork, cudaEventDisableTiming);
        cudaEventCreateWithFlags(&g_evPrep, cudaEventDisableTiming);
        cudaEventCreateWithFlags(&g_evT1, cudaEventDisableTiming);
    }
} g_stream_init;

// ======================= helpers ==========================================
__device__ __forceinline__ void split4(float4 v, uint32_t& h01, uint32_t& h23,
                                       uint32_t& l01, uint32_t& l23)
{
    asm("cvt.rn.bf16x2.f32 %0, %1, %2;" : "=r"(h01) : "f"(v.y), "f"(v.x));
    asm("cvt.rn.bf16x2.f32 %0, %1, %2;" : "=r"(h23) : "f"(v.w), "f"(v.z));
    float r0 = v.x - __uint_as_float(h01 << 16);
    float r1 = v.y - __uint_as_float(h01 & 0xFFFF0000u);
    float r2 = v.z - __uint_as_float(h23 << 16);
    float r3 = v.w - __uint_as_float(h23 & 0xFFFF0000u);
    asm("cvt.rn.bf16x2.f32 %0, %1, %2;" : "=r"(l01) : "f"(r1), "f"(r0));
    asm("cvt.rn.bf16x2.f32 %0, %1, %2;" : "=r"(l23) : "f"(r3), "f"(r2));
}

__device__ __forceinline__ void sts_v2(uint32_t addr, uint32_t a, uint32_t b) {
    asm volatile("st.shared.v2.b32 [%0], {%1,%2};" :: "r"(addr), "r"(a), "r"(b) : "memory");
}

__device__ __forceinline__ uint32_t smem_u32(const void* p) {
    uint32_t a;
    asm("{ .reg .u64 t; cvta.to.shared.u64 t, %1; cvt.u32.u64 %0, t; }"
        : "=r"(a) : "l"(p));
    return a;
}

__device__ __forceinline__ void cp_async16(uint32_t dst, const void* src) {
    asm volatile("cp.async.cg.shared.global [%0], [%1], 16;"
                 :: "r"(dst), "l"(src) : "memory");
}
__device__ __forceinline__ void cp_commit() {
    asm volatile("cp.async.commit_group;" ::: "memory");
}
__device__ __forceinline__ void cp_wait_all() {
    asm volatile("cp.async.wait_group 0;" ::: "memory");
}
__device__ __forceinline__ void cp_wait1() {
    asm volatile("cp.async.wait_group 1;" ::: "memory");
}

// ======================= weight prep kernels ===============================
__global__ void conv_w_kernel(const float* __restrict__ src,
                              __nv_bfloat16* __restrict__ hi,
                              __nv_bfloat16* __restrict__ lo, int n)
{
    int i = (blockIdx.x * 256 + threadIdx.x) * 4;
    if (i >= n) return;
    float4 v = *(const float4*)(src + i);
    uint32_t h01, h23, l01, l23;
    split4(v, h01, h23, l01, l23);
    *(uint2*)((char*)hi + (size_t)i * 2) = make_uint2(h01, h23);
    *(uint2*)((char*)lo + (size_t)i * 2) = make_uint2(l01, l23);
}

__global__ void conv_ow_kernel(const float* __restrict__ off_w,
                               const float* __restrict__ aw_w)
{
    int idx = (blockIdx.x * 256 + threadIdx.x) * 4;
    if (idx >= 3 * 96 * 256) return;
    int layer = idx / (96 * 256);
    int rem = idx - layer * 96 * 256;
    int r = rem >> 8, c = rem & 255;
    const float* src = (r < 64)
        ? off_w + ((size_t)layer * 64 + r) * 256 + c
        : aw_w + ((size_t)layer * 32 + (r - 64)) * 256 + c;
    float4 v = *(const float4*)src;
    uint32_t h01, h23, l01, l23;
    split4(v, h01, h23, l01, l23);
    *(uint2*)((char*)&g_ow_hi[layer][rem]) = make_uint2(h01, h23);
    *(uint2*)((char*)&g_ow_lo[layer][rem]) = make_uint2(l01, l23);
}

__global__ void conv_obias_kernel(const float* __restrict__ off_b,
                                  const float* __restrict__ aw_b)
{
    int idx = threadIdx.x;
    if (idx >= 3 * 96) return;
    int layer = idx / 96, r = idx % 96;
    g_obias[layer][r] = (r < 64) ? off_b[layer * 64 + r] : aw_b[layer * 32 + (r - 64)];
}

// ======================= WMMA bf16x3 GEMM (512 threads, KCH=32) ============
// CTA tile 128 x BN; per-batch M with mEnd write guard.
// AMODE: 0 = A row-major [M,256] ; 1 = same + pos added ;
//        2 = A is TRANSPOSED source [256, HWn] (e.g. bev) — fused transpose.
// EPI: 0 = bias(+relu) -> C ; 1 = bias, split 64/32 -> C,C2 ;
//      2 = bias + residual + LayerNorm -> R (in place)
template<int BN, int AMODE, bool RELU, int EPI>
__global__ __launch_bounds__(512)
void wgemm(const float* __restrict__ A,
           const __nv_bfloat16* __restrict__ Bh,
           const __nv_bfloat16* __restrict__ Bl,
           const float* __restrict__ bias, float* __restrict__ C,
           float* __restrict__ C2, const float* __restrict__ pos,
           float* __restrict__ R, const float* __restrict__ lng,
           const float* __restrict__ lnb, int mEnd)
{
    constexpr int K = 256, KCH = 32, NCHUNK = K / KCH;
    constexpr int BM = 128;
    constexpr int WARPS_N = (BN == 256) ? 4 : 2;
    constexpr int WARPS_M = 16 / WARPS_N;
    constexpr int MF = (BM / WARPS_M) / 16;
    constexpr int NF = (BN / WARPS_N) / 16;
    constexpr int STR = 40;                       // row-major A k-stride
    constexpr int ATSTR = 136;                    // trans A m-stride ([k][m])
    constexpr int ABYTES = (AMODE == 2) ? (KCH * ATSTR * 2) : (BM * STR * 2);
    constexpr int BBYTES = BN * STR * 2;
    constexpr int STAGE = 2 * ABYTES + 2 * BBYTES;

    extern __shared__ char smem[];
    uint32_t sbase = smem_u32(smem);
    float* cs = (float*)smem;

    int tid = threadIdx.x;
    int w = tid >> 5;
    int lane = tid & 31;
    int wm0 = (w / WARPS_N) * (BM / WARPS_M);
    int wn0 = (w % WARPS_N) * (BN / WARPS_N);
    int m0 = blockIdx.x * BM;

    wmma::fragment<wmma::accumulator, 16, 16, 16, float> acc[MF][NF];
#pragma unroll
    for (int i = 0; i < MF; i++)
#pragma unroll
        for (int j = 0; j < NF; j++) wmma::fill_fragment(acc[i][j], 0.f);

    float4 areg[2];
    auto load_A = [&](int c) {
        int k0 = c * KCH;
#pragma unroll
        for (int it = 0; it < 2; it++) {
            int idx = tid + it * 512;
            if (AMODE == 2) {
                int k = idx >> 5;               // 0..31
                int mq = idx & 31;              // 0..31 -> 4 m each
                int m = m0 + mq * 4;
                if (m + 3 >= mEnd) m = mEnd - 4;   // clamp (writes guarded)
                areg[it] = *(const float4*)(A + (size_t)(k0 + k) * HWn + m);
            } else {
                int row = idx >> 3;
                int c4 = (idx & 7) << 2;
                int m = m0 + row;
                float4 v = *(const float4*)(A + (size_t)m * K + k0 + c4);
                if (AMODE == 1) {
                    int pm = m - (m >= HWn ? HWn : 0);
                    float4 p = *(const float4*)(pos + (size_t)pm * K + k0 + c4);
                    v.x += p.x; v.y += p.y; v.z += p.z; v.w += p.w;
                }
                areg[it] = v;
            }
        }
    };
    auto sts_A = [&](int c) {
        uint32_t a_hi = sbase + (c & 1) * STAGE;
        uint32_t a_lo = a_hi + ABYTES;
#pragma unroll
        for (int it = 0; it < 2; it++) {
            int idx = tid + it * 512;
            uint32_t h01, h23, l01, l23;
            split4(areg[it], h01, h23, l01, l23);
            if (AMODE == 2) {
                int k = idx >> 5;
                int mq = idx & 31;
                uint32_t off = (uint32_t)(k * ATSTR + mq * 4) * 2;
                sts_v2(a_hi + off, h01, h23);
                sts_v2(a_lo + off, l01, l23);
            } else {
                int row = idx >> 3;
                int c4 = (idx & 7) << 2;
                uint32_t off = (uint32_t)(row * STR + c4) * 2;
                sts_v2(a_hi + off, h01, h23);
                sts_v2(a_lo + off, l01, l23);
            }
        }
    };
    auto cp_B = [&](int c) {
        int k0 = c * KCH;
        uint32_t b_hi = sbase + (c & 1) * STAGE + 2 * ABYTES;
        constexpr int OPS = BN * 4 * 2;
#pragma unroll
        for (int it = 0; it < (OPS + 511) / 512; it++) {
            int idx = tid + it * 512;
            if (OPS % 512 && idx >= OPS) break;
            int half = idx / (BN * 4);
            int rem = idx - half * (BN * 4);
            int r = rem >> 2, ch = rem & 3;
            const __nv_bfloat16* src =
                (half ? Bl : Bh) + (size_t)r * K + k0 + ch * 8;
            cp_async16(b_hi + half * BBYTES + (uint32_t)(r * STR + ch * 8) * 2, src);
        }
        cp_commit();
    };

    load_A(0);
    sts_A(0);
    cp_B(0);

    for (int c = 0; c < NCHUNK; c++) {
        cp_wait_all();
        __syncthreads();
        if (c + 1 < NCHUNK) { cp_B(c + 1); load_A(c + 1); }

        const __nv_bfloat16* a_hi =
            (const __nv_bfloat16*)(smem + (c & 1) * STAGE);
        const __nv_bfloat16* b_base =
            (const __nv_bfloat16*)(smem + (c & 1) * STAGE + 2 * ABYTES);
#pragma unroll
        for (int ks = 0; ks < 2; ks++) {
            if (AMODE == 2) {
                wmma::fragment<wmma::matrix_a, 16, 16, 16, __nv_bfloat16, wmma::col_major> ah[MF], al[MF];
#pragma unroll
                for (int i = 0; i < MF; i++) {
                    const __nv_bfloat16* pa = a_hi + (ks * 16) * ATSTR + wm0 + i * 16;
                    wmma::load_matrix_sync(ah[i], pa, ATSTR);
                    wmma::load_matrix_sync(al[i], pa + KCH * ATSTR, ATSTR);
                }
#pragma unroll
                for (int j = 0; j < NF; j++) {
                    wmma::fragment<wmma::matrix_b, 16, 16, 16, __nv_bfloat16, wmma::col_major> bh, bl;
                    const __nv_bfloat16* pb = b_base + (wn0 + j * 16) * STR + ks * 16;
                    wmma::load_matrix_sync(bh, pb, STR);
                    wmma::load_matrix_sync(bl, pb + BN * STR, STR);
#pragma unroll
                    for (int i = 0; i < MF; i++) {
                        wmma::mma_sync(acc[i][j], ah[i], bh, acc[i][j]);
                        wmma::mma_sync(acc[i][j], ah[i], bl, acc[i][j]);
                        wmma::mma_sync(acc[i][j], al[i], bh, acc[i][j]);
                    }
                }
            } else {
                wmma::fragment<wmma::matrix_a, 16, 16, 16, __nv_bfloat16, wmma::row_major> ah[MF], al[MF];
#pragma unroll
                for (int i = 0; i < MF; i++) {
                    const __nv_bfloat16* pa = a_hi + (wm0 + i * 16) * STR + ks * 16;
                    wmma::load_matrix_sync(ah[i], pa, STR);
                    wmma::load_matrix_sync(al[i], pa + BM * STR, STR);
                }
#pragma unroll
                for (int j = 0; j < NF; j++) {
                    wmma::fragment<wmma::matrix_b, 16, 16, 16, __nv_bfloat16, wmma::col_major> bh, bl;
                    const __nv_bfloat16* pb = b_base + (wn0 + j * 16) * STR + ks * 16;
                    wmma::load_matrix_sync(bh, pb, STR);
                    wmma::load_matrix_sync(bl, pb + BN * STR, STR);
#pragma unroll
                    for (int i = 0; i < MF; i++) {
                        wmma::mma_sync(acc[i][j], ah[i], bh, acc[i][j]);
                        wmma::mma_sync(acc[i][j], ah[i], bl, acc[i][j]);
                        wmma::mma_sync(acc[i][j], al[i], bh, acc[i][j]);
                    }
                }
            }
        }
        if (c + 1 < NCHUNK) sts_A(c + 1);
    }

    __syncthreads();
#pragma unroll
    for (int i = 0; i < MF; i++)
#pragma unroll
        for (int j = 0; j < NF; j++)
            wmma::store_matrix_sync(cs + (wm0 + i * 16) * (BN + 4) + wn0 + j * 16,
                                    acc[i][j], BN + 4, wmma::mem_row_major);
    __syncthreads();

    if (EPI == 2) {
#pragma unroll
        for (int r8 = 0; r8 < BM / 16; r8++) {
            int row = w * (BM / 16) + r8;
            int m = m0 + row;
            if (m >= mEnd) continue;
            float* rp = R + (size_t)m * 256 + lane * 8;
            const float* csr = cs + row * (BN + 4) + lane * 8;
            float v[8];
            float4 c0 = *(const float4*)(csr);
            float4 c1 = *(const float4*)(csr + 4);
            float4 q0 = *(const float4*)(rp);
            float4 q1 = *(const float4*)(rp + 4);
            float4 b0 = *(const float4*)(bias + lane * 8);
            float4 b1 = *(const float4*)(bias + lane * 8 + 4);
            v[0] = c0.x + q0.x + b0.x; v[1] = c0.y + q0.y + b0.y;
            v[2] = c0.z + q0.z + b0.z; v[3] = c0.w + q0.w + b0.w;
            v[4] = c1.x + q1.x + b1.x; v[5] = c1.y + q1.y + b1.y;
            v[6] = c1.z + q1.z + b1.z; v[7] = c1.w + q1.w + b1.w;
            float s = 0.f;
#pragma unroll
            for (int i = 0; i < 8; i++) s += v[i];
#pragma unroll
            for (int o = 16; o > 0; o >>= 1) s += __shfl_xor_sync(0xffffffffu, s, o);
            float mean = s * (1.f / 256.f);
            float s2 = 0.f;
#pragma unroll
            for (int i = 0; i < 8; i++) { float d = v[i] - mean; s2 += d * d; }
#pragma unroll
            for (int o = 16; o > 0; o >>= 1) s2 += __shfl_xor_sync(0xffffffffu, s2, o);
            float inv = rsqrtf(s2 * (1.f / 256.f) + 1e-5f);
            float4 g0 = *(const float4*)(lng + lane * 8);
            float4 g1 = *(const float4*)(lng + lane * 8 + 4);
            float4 t0 = *(const float4*)(lnb + lane * 8);
            float4 t1 = *(const float4*)(lnb + lane * 8 + 4);
            float4 o0, o1;
            o0.x = (v[0] - mean) * inv * g0.x + t0.x;
            o0.y = (v[1] - mean) * inv * g0.y + t0.y;
            o0.z = (v[2] - mean) * inv * g0.z + t0.z;
            o0.w = (v[3] - mean) * inv * g0.w + t0.w;
            o1.x = (v[4] - mean) * inv * g1.x + t1.x;
            o1.y = (v[5] - mean) * inv * g1.y + t1.y;
            o1.z = (v[6] - mean) * inv * g1.z + t1.z;
            o1.w = (v[7] - mean) * inv * g1.w + t1.w;
            *(float4*)(rp) = o0;
            *(float4*)(rp + 4) = o1;
        }
    } else {
        constexpr int ITERS = (BM * BN / 4) / 512;
#pragma unroll
        for (int it = 0; it < ITERS; it++) {
            int idx = tid + it * 512;
            int row = idx / (BN / 4);
            int c4  = (idx % (BN / 4)) * 4;
            int m = m0 + row;
            if (m >= mEnd) continue;
            float4 o = *(const float4*)(cs + row * (BN + 4) + c4);
            o.x += __ldg(bias + c4 + 0);
            o.y += __ldg(bias + c4 + 1);
            o.z += __ldg(bias + c4 + 2);
            o.w += __ldg(bias + c4 + 3);
            if (RELU) {
                o.x = fmaxf(o.x, 0.f); o.y = fmaxf(o.y, 0.f);
                o.z = fmaxf(o.z, 0.f); o.w = fmaxf(o.w, 0.f);
            }
            if (EPI == 1) {
                if (c4 < 64) *(float4*)(C  + (size_t)m * 64 + c4)        = o;
                else         *(float4*)(C2 + (size_t)m * 32 + (c4 - 64)) = o;
            } else {
                *(float4*)(C + (size_t)m * BN + c4) = o;
            }
        }
    }
}

constexpr int wg_smem(int bn) {
    int stage = (2 * 128 + 2 * bn) * 40 * 2;
    int ab = 2 * stage;
    int cb = 128 * (bn + 4) * 4;
    return ab > cb ? ab : cb;
}

// ======================= fused FFN kernel (KCH=32) =========================
// out = LN(out + relu(out@l1^T + b1) @ l2^T + b2)
// If T != nullptr: write LN result TRANSPOSED to T[c][m] (fused final transpose).
__global__ __launch_bounds__(512)
void wgemm_ffn(float* __restrict__ A,
               const __nv_bfloat16* __restrict__ B1h, const __nv_bfloat16* __restrict__ B1l,
               const float* __restrict__ b1,
               const __nv_bfloat16* __restrict__ B2h, const __nv_bfloat16* __restrict__ B2l,
               const float* __restrict__ b2,
               const float* __restrict__ lng, const float* __restrict__ lnb,
               int mEnd, float* __restrict__ T)
{
    constexpr int K = 256, KCH = 32, NCHUNK = 8, BM = 128, BN = 256;
    constexpr int WARPS_N = 4, MF = 2, NF = 4;
    constexpr int STR = 40;
    constexpr int ABYTES = BM * STR * 2;
    constexpr int BBYTES = BN * STR * 2;
    constexpr int STAGE = 2 * ABYTES + 2 * BBYTES;
    constexpr int STR2 = 264;
    constexpr int A2_SPLIT = BM * STR2 * 2;
    constexpr int CSH_OFF = 2 * A2_SPLIT;
    constexpr int B2_STAGE = 2 * BBYTES;

    extern __shared__ char smem[];
    uint32_t sbase = smem_u32(smem);
    float* cs = (float*)smem;
    float* csh = (float*)(smem + CSH_OFF);

    int tid = threadIdx.x;
    int w = tid >> 5;
    int lane = tid & 31;
    int wm0 = (w / WARPS_N) * 32;
    int wn0 = (w % WARPS_N) * 64;
    int m0 = blockIdx.x * BM;

    wmma::fragment<wmma::accumulator, 16, 16, 16, float> acc[MF][NF];
#pragma unroll
    for (int i = 0; i < MF; i++)
#pragma unroll
        for (int j = 0; j < NF; j++) wmma::fill_fragment(acc[i][j], 0.f);

    float4 areg[2];
    auto load_A = [&](int c) {
        int k0 = c * KCH;
#pragma unroll
        for (int it = 0; it < 2; it++) {
            int idx = tid + it * 512;
            int row = idx >> 3;
            int c4 = (idx & 7) << 2;
            areg[it] = *(const float4*)(A + (size_t)(m0 + row) * K + k0 + c4);
        }
    };
    auto sts_A = [&](int c) {
        uint32_t a_hi = sbase + (c & 1) * STAGE;
        uint32_t a_lo = a_hi + ABYTES;
#pragma unroll
        for (int it = 0; it < 2; it++) {
            int idx = tid + it * 512;
            int row = idx >> 3;
            int c4 = (idx & 7) << 2;
            uint32_t h01, h23, l01, l23;
            split4(areg[it], h01, h23, l01, l23);
            uint32_t off = (uint32_t)(row * STR + c4) * 2;
            sts_v2(a_hi + off, h01, h23);
            sts_v2(a_lo + off, l01, l23);
        }
    };
    auto cp_B1 = [&](int c) {
        int k0 = c * KCH;
        uint32_t b_hi = sbase + (c & 1) * STAGE + 2 * ABYTES;
#pragma unroll
        for (int it = 0; it < 4; it++) {
            int idx = tid + it * 512;
            int half = idx >> 10;
            int rem = idx & 1023;
            int r = rem >> 2, ch = rem & 3;
            const __nv_bfloat16* src =
                (half ? B1l : B1h) + (size_t)r * K + k0 + ch * 8;
            cp_async16(b_hi + half * BBYTES + (uint32_t)(r * STR + ch * 8) * 2, src);
        }
        cp_commit();
    };

    load_A(0);
    sts_A(0);
    cp_B1(0);

    for (int c = 0; c < NCHUNK; c++) {
        cp_wait_all();
        __syncthreads();
        if (c + 1 < NCHUNK) { cp_B1(c + 1); load_A(c + 1); }

        const __nv_bfloat16* a_hi = (const __nv_bfloat16*)(smem + (c & 1) * STAGE);
        const __nv_bfloat16* b_base = (const __nv_bfloat16*)(smem + (c & 1) * STAGE + 2 * ABYTES);
#pragma unroll
        for (int ks = 0; ks < 2; ks++) {
            wmma::fragment<wmma::matrix_a, 16, 16, 16, __nv_bfloat16, wmma::row_major> ah[MF], al[MF];
#pragma unroll
            for (int i = 0; i < MF; i++) {
                const __nv_bfloat16* pa = a_hi + (wm0 + i * 16) * STR + ks * 16;
                wmma::load_matrix_sync(ah[i], pa, STR);
                wmma::load_matrix_sync(al[i], pa + BM * STR, STR);
            }
#pragma unroll
            for (int j = 0; j < NF; j++) {
                wmma::fragment<wmma::matrix_b, 16, 16, 16, __nv_bfloat16, wmma::col_major> bh, bl;
                const __nv_bfloat16* pb = b_base + (wn0 + j * 16) * STR + ks * 16;
                wmma::load_matrix_sync(bh, pb, STR);
                wmma::load_matrix_sync(bl, pb + BN * STR, STR);
#pragma unroll
                for (int i = 0; i < MF; i++) {
                    wmma::mma_sync(acc[i][j], ah[i], bh, acc[i][j]);
                    wmma::mma_sync(acc[i][j], ah[i], bl, acc[i][j]);
                    wmma::mma_sync(acc[i][j], al[i], bh, acc[i][j]);
                }
            }
        }
        if (c + 1 < NCHUNK) sts_A(c + 1);
    }

    // convert ffn1 -> bf16 hi/lo tile in smem
#pragma unroll
    for (int half = 0; half < 2; half++) {
        __syncthreads();
        if ((wn0 < 128) == (half == 0)) {
            int lwn = wn0 - half * 128;
#pragma unroll
            for (int i = 0; i < MF; i++)
#pragma unroll
                for (int j = 0; j < NF; j++)
                    wmma::store_matrix_sync(csh + (wm0 + i * 16) * 132 + lwn + j * 16,
                                            acc[i][j], 132, wmma::mem_row_major);
        }
        __syncthreads();
#pragma unroll
        for (int it = 0; it < 8; it++) {
            int idx = tid + it * 512;
            int row = idx >> 5;
            int lc4 = (idx & 31) << 2;
            int gcol = half * 128 + lc4;
            float4 o = *(const float4*)(csh + row * 132 + lc4);
            o.x = fmaxf(o.x + __ldg(b1 + gcol + 0), 0.f);
            o.y = fmaxf(o.y + __ldg(b1 + gcol + 1), 0.f);
            o.z = fmaxf(o.z + __ldg(b1 + gcol + 2), 0.f);
            o.w = fmaxf(o.w + __ldg(b1 + gcol + 3), 0.f);
            uint32_t h01, h23, l01, l23;
            split4(o, h01, h23, l01, l23);
            uint32_t off = (uint32_t)(row * STR2 + gcol) * 2;
            sts_v2(sbase + off, h01, h23);
            sts_v2(sbase + A2_SPLIT + off, l01, l23);
        }
    }
    __syncthreads();

    // GEMM2: ffn1 @ l2^T
#pragma unroll
    for (int i = 0; i < MF; i++)
#pragma unroll
        for (int j = 0; j < NF; j++) wmma::fill_fragment(acc[i][j], 0.f);

    auto cp_B2 = [&](int c) {
        int k0 = c * KCH;
        uint32_t st = sbase + CSH_OFF + (c & 1) * B2_STAGE;
#pragma unroll
        for (int it = 0; it < 4; it++) {
            int idx = tid + it * 512;
            int half = idx >> 10;
            int rem = idx & 1023;
            int r = rem >> 2, ch = rem & 3;
            const __nv_bfloat16* src =
                (half ? B2l : B2h) + (size_t)r * K + k0 + ch * 8;
            cp_async16(st + half * BBYTES + (uint32_t)(r * STR + ch * 8) * 2, src);
        }
        cp_commit();
    };

    cp_B2(0);
    cp_B2(1);

    const __nv_bfloat16* a2h = (const __nv_bfloat16*)smem;
    for (int c = 0; c < NCHUNK; c++) {
        if (c < NCHUNK - 2) { cp_wait1(); } else { cp_wait_all(); }
        __syncthreads();

        const __nv_bfloat16* b_base =
            (const __nv_bfloat16*)(smem + CSH_OFF + (c & 1) * B2_STAGE);
#pragma unroll
        for (int ks = 0; ks < 2; ks++) {
            int kc = c * KCH + ks * 16;
            wmma::fragment<wmma::matrix_a, 16, 16, 16, __nv_bfloat16, wmma::row_major> ah[MF], al[MF];
#pragma unroll
            for (int i = 0; i < MF; i++) {
                const __nv_bfloat16* pa = a2h + (wm0 + i * 16) * STR2 + kc;
                wmma::load_matrix_sync(ah[i], pa, STR2);
                wmma::load_matrix_sync(al[i], pa + BM * STR2, STR2);
            }
#pragma unroll
            for (int j = 0; j < NF; j++) {
                wmma::fragment<wmma::matrix_b, 16, 16, 16, __nv_bfloat16, wmma::col_major> bh, bl;
                const __nv_bfloat16* pb = b_base + (wn0 + j * 16) * STR + ks * 16;
                wmma::load_matrix_sync(bh, pb, STR);
                wmma::load_matrix_sync(bl, pb + BN * STR, STR);
#pragma unroll
                for (int i = 0; i < MF; i++) {
                    wmma::mma_sync(acc[i][j], ah[i], bh, acc[i][j]);
                    wmma::mma_sync(acc[i][j], ah[i], bl, acc[i][j]);
                    wmma::mma_sync(acc[i][j], al[i], bh, acc[i][j]);
                }
            }
        }
        __syncthreads();
        if (c + 2 < NCHUNK) cp_B2(c + 2);
    }

    // LN epilogue
    __syncthreads();
#pragma unroll
    for (int i = 0; i < MF; i++)
#pragma unroll
        for (int j = 0; j < NF; j++)
            wmma::store_matrix_sync(cs + (wm0 + i * 16) * (BN + 4) + wn0 + j * 16,
                                    acc[i][j], BN + 4, wmma::mem_row_major);
    __syncthreads();

#pragma unroll
    for (int r8 = 0; r8 < BM / 16; r8++) {
        int row = w * (BM / 16) + r8;
        int m = m0 + row;
        if (m >= mEnd) continue;
        float* rp = A + (size_t)m * 256 + lane * 8;
        float* csr = cs + row * (BN + 4) + lane * 8;
        float v[8];
        float4 c0 = *(const float4*)(csr);
        float4 c1 = *(const float4*)(csr + 4);
        float4 q0 = *(const float4*)(rp);
        float4 q1 = *(const float4*)(rp + 4);
        float4 b0 = *(const float4*)(b2 + lane * 8);
        float4 b1v = *(const float4*)(b2 + lane * 8 + 4);
        v[0] = c0.x + q0.x + b0.x; v[1] = c0.y + q0.y + b0.y;
        v[2] = c0.z + q0.z + b0.z; v[3] = c0.w + q0.w + b0.w;
        v[4] = c1.x + q1.x + b1v.x; v[5] = c1.y + q1.y + b1v.y;
        v[6] = c1.z + q1.z + b1v.z; v[7] = c1.w + q1.w + b1v.w;
        float s = 0.f;
#pragma unroll
        for (int i = 0; i < 8; i++) s += v[i];
#pragma unroll
        for (int o = 16; o > 0; o >>= 1) s += __shfl_xor_sync(0xffffffffu, s, o);
        float mean = s * (1.f / 256.f);
        float s2 = 0.f;
#pragma unroll
        for (int i = 0; i < 8; i++) { float d = v[i] - mean; s2 += d * d; }
#pragma unroll
        for (int o = 16; o > 0; o >>= 1) s2 += __shfl_xor_sync(0xffffffffu, s2, o);
        float inv = rsqrtf(s2 * (1.f / 256.f) + 1e-5f);
        float4 g0 = *(const float4*)(lng + lane * 8);
        float4 g1 = *(const float4*)(lng + lane * 8 + 4);
        float4 t0 = *(const float4*)(lnb + lane * 8);
        float4 t1 = *(const float4*)(lnb + lane * 8 + 4);
        float4 o0, o1;
        o0.x = (v[0] - mean) * inv * g0.x + t0.x;
        o0.y = (v[1] - mean) * inv * g0.y + t0.y;
        o0.z = (v[2] - mean) * inv * g0.z + t0.z;
        o0.w = (v[3] - mean) * inv * g0.w + t0.w;
        o1.x = (v[4] - mean) * inv * g1.x + t1.x;
        o1.y = (v[5] - mean) * inv * g1.y + t1.y;
        o1.z = (v[6] - mean) * inv * g1.z + t1.z;
        o1.w = (v[7] - mean) * inv * g1.w + t1.w;
        if (T) {
            *(float4*)(csr) = o0;
            *(float4*)(csr + 4) = o1;
        } else {
            *(float4*)(rp) = o0;
            *(float4*)(rp + 4) = o1;
        }
    }

    if (T) {
        __syncthreads();
#pragma unroll
        for (int it = 0; it < 16; it++) {
            int idx = tid + it * 512;
            int c = idx >> 5;
            int rq = idx & 31;
            int m = m0 + rq * 4;
            if (m < mEnd) {
                float4 o;
                o.x = cs[(rq * 4 + 0) * (BN + 4) + c];
                o.y = cs[(rq * 4 + 1) * (BN + 4) + c];
                o.z = cs[(rq * 4 + 2) * (BN + 4) + c];
                o.w = cs[(rq * 4 + 3) * (BN + 4) + c];
                *(float4*)(T + (size_t)c * HWn + m) = o;
            }
        }
    }
}

constexpr int FFN_SMEM = 2 * (128 * 264 * 2) + 2 * (2 * 256 * 40 * 2);

// ======================= sine positional encoding ==========================
__global__ void pos_kernel(float* __restrict__ pos)
{
    int q = blockIdx.x;
    int c = threadIdx.x;
    int row = q / Wn, col = q % Wn;
    int cc = c;
    float v;
    if (cc < 128) { v = (float)(row + 1); }
    else          { v = (float)(col + 1); cc -= 128; }
    int j = cc >> 1;
    float t = powf(10000.f, (float)(2 * j) * (1.f / 128.f));
    float arg = v / t;
    pos[(size_t)q * Cn + c] = (cc & 1) ? cosf(arg) : sinf(arg);
}

// ======================= deformable sampling (single batch) ================
__global__ __launch_bounds__(256)
void sample_kernel(const float* __restrict__ value, const float* __restrict__ off,
                   const float* __restrict__ aw, float* __restrict__ attn)
{
    int q = blockIdx.x;
    int h = threadIdx.x >> 5;
    int lane = threadIdx.x & 31;
    size_t base = (size_t)q;

    const float* awp = aw + base * 32 + h * 4;
    float a0 = awp[0], a1 = awp[1], a2 = awp[2], a3 = awp[3];
    float mx = fmaxf(fmaxf(a0, a1), fmaxf(a2, a3));
    float e0 = expf(a0 - mx), e1 = expf(a1 - mx), e2 = expf(a2 - mx), e3 = expf(a3 - mx);
    float inv = 1.f / (e0 + e1 + e2 + e3);
    float wp[4] = {e0 * inv, e1 * inv, e2 * inv, e3 * inv};

    const float* offp = off + base * 64 + h * 8;
    int col = q % Wn, row = q / Wn;
    const float* vb = value + h * HDn + lane;

    float acc = 0.f;
#pragma unroll
    for (int p = 0; p < 4; p++) {
        float x = (float)col + offp[p * 2 + 0];
        float y = (float)row + offp[p * 2 + 1];
        float xf = floorf(x), yf = floorf(y);
        int x0 = (int)xf, y0 = (int)yf;
        float wx = x - xf, wy = y - yf;
        float w00 = (1.f - wx) * (1.f - wy), w10 = wx * (1.f - wy);
        float w01 = (1.f - wx) * wy,         w11 = wx * wy;
        float s = 0.f;
        if ((unsigned)x0 < (unsigned)Wn && (unsigned)y0 < (unsigned)Hn)
            s += w00 * vb[(size_t)(y0 * Wn + x0) * Cn];
        if ((unsigned)(x0 + 1) < (unsigned)Wn && (unsigned)y0 < (unsigned)Hn)
            s += w10 * vb[(size_t)(y0 * Wn + x0 + 1) * Cn];
        if ((unsigned)x0 < (unsigned)Wn && (unsigned)(y0 + 1) < (unsigned)Hn)
            s += w01 * vb[(size_t)((y0 + 1) * Wn + x0) * Cn];
        if ((unsigned)(x0 + 1) < (unsigned)Wn && (unsigned)(y0 + 1) < (unsigned)Hn)
            s += w11 * vb[(size_t)((y0 + 1) * Wn + x0 + 1) * Cn];
        acc += wp[p] * s;
    }
    attn[base * Cn + h * HDn + lane] = acc;
}

// ======================= launch ===========================================
extern "C" void kernel_launch(void* const* d_in, const int* in_sizes, int n_in,
                              void* d_out, int out_size)
{
    const float* bev      = (const float*)d_in[0];
    const float* proj_q_w = (const float*)d_in[1];
    const float* proj_q_b = (const float*)d_in[2];
    const float* off_w    = (const float*)d_in[3];
    const float* off_b    = (const float*)d_in[4];
    const float* aw_w     = (const float*)d_in[5];
    const float* aw_b     = (const float*)d_in[6];
    const float* vp_w     = (const float*)d_in[7];
    const float* vp_b     = (const float*)d_in[8];
    const float* op_w     = (const float*)d_in[9];
    const float* op_b     = (const float*)d_in[10];
    const float* ln1_g    = (const float*)d_in[11];
    const float* ln1_b    = (const float*)d_in[12];
    const float* l1_w     = (const float*)d_in[13];
    const float* l1_b     = (const float*)d_in[14];
    const float* l2_w     = (const float*)d_in[15];
    const float* l2_b     = (const float*)d_in[16];
    const float* ln2_g    = (const float*)d_in[17];
    const float* ln2_b    = (const float*)d_in[18];
    float* out_final      = (float*)d_out;

    float *out, *pos, *val, *attn, *offb, *awb, *obias;
    __nv_bfloat16 *wbh, *wbl, *owh, *owl;
    cudaGetSymbolAddress((void**)&out,  g_out);
    cudaGetSymbolAddress((void**)&pos,  g_pos);
    cudaGetSymbolAddress((void**)&val,  g_val);
    cudaGetSymbolAddress((void**)&attn, g_attn);
    cudaGetSymbolAddress((void**)&offb, g_off);
    cudaGetSymbolAddress((void**)&awb,  g_aw);
    cudaGetSymbolAddress((void**)&wbh, g_wb_hi);
    cudaGetSymbolAddress((void**)&wbl, g_wb_lo);
    cudaGetSymbolAddress((void**)&owh, g_ow_hi);
    cudaGetSymbolAddress((void**)&owl, g_ow_lo);
    cudaGetSymbolAddress((void**)&obias, g_obias);

    cudaFuncSetAttribute((const void*)wgemm<256, 2, false, 0>,
                         cudaFuncAttributeMaxDynamicSharedMemorySize, wg_smem(256));
    cudaFuncSetAttribute((const void*)wgemm<256, 0, false, 0>,
                         cudaFuncAttributeMaxDynamicSharedMemorySize, wg_smem(256));
    cudaFuncSetAttribute((const void*)wgemm<256, 0, false, 2>,
                         cudaFuncAttributeMaxDynamicSharedMemorySize, wg_smem(256));
    cudaFuncSetAttribute((const void*)wgemm<96, 1, false, 1>,
                         cudaFuncAttributeMaxDynamicSharedMemorySize, wg_smem(96));
    cudaFuncSetAttribute((const void*)wgemm_ffn,
                         cudaFuncAttributeMaxDynamicSharedMemorySize, FFN_SMEM);

    const int MBb = (HWn + 127) / 128;     // 313 CTAs per batch

    cudaStream_t sb[2] = { (cudaStream_t)0, g_s2 };

    // ---- fork prep stream (all weight conversion + pos)
    cudaEventRecord(g_evFork, 0);
    cudaStreamWaitEvent(g_s3, g_evFork, 0);
    cudaStreamWaitEvent(g_s2, g_evFork, 0);
    conv_w_kernel<<<64, 256, 0, g_s3>>>(proj_q_w, wbh + 0 * 65536, wbl + 0 * 65536, 65536);
    conv_w_kernel<<<192, 256, 0, g_s3>>>(vp_w, wbh + 1 * 65536, wbl + 1 * 65536, 3 * 65536);
    conv_w_kernel<<<192, 256, 0, g_s3>>>(op_w, wbh + 4 * 65536, wbl + 4 * 65536, 3 * 65536);
    conv_w_kernel<<<192, 256, 0, g_s3>>>(l1_w, wbh + 7 * 65536, wbl + 7 * 65536, 3 * 65536);
    conv_w_kernel<<<192, 256, 0, g_s3>>>(l2_w, wbh + 10 * 65536, wbl + 10 * 65536, 3 * 65536);
    conv_ow_kernel<<<72, 256, 0, g_s3>>>(off_w, aw_w);
    conv_obias_kernel<<<1, 288, 0, g_s3>>>(off_b, aw_b);
    pos_kernel<<<HWn, 256, 0, g_s3>>>(pos);
    cudaEventRecord(g_evPrep, g_s3);

    cudaStreamWaitEvent(sb[0], g_evPrep, 0);
    cudaStreamWaitEvent(sb[1], g_evPrep, 0);

    // ---- per-batch chains on two streams
    for (int b = 0; b < BSn; b++) {
        cudaStream_t s = sb[b];
        size_t ro = (size_t)b * HWn;                 // row offset
        float* out_b  = out  + ro * Cn;
        float* val_b  = val  + ro * Cn;
        float* attn_b = attn + ro * Cn;
        float* offb_b = offb + ro * 64;
        float* awb_b  = awb  + ro * 32;
        const float* bev_b = bev + (size_t)b * Cn * HWn;

        // proj: reads bev [C][HW] directly (fused input transpose)
        wgemm<256, 2, false, 0><<<MBb, 512, wg_smem(256), s>>>(
            bev_b, wbh + 0 * 65536, wbl + 0 * 65536, proj_q_b, out_b,
            nullptr, nullptr, nullptr, nullptr, nullptr, HWn);

        for (int i = 0; i < NLAYERS; i++) {
            wgemm<256, 0, false, 0><<<MBb, 512, wg_smem(256), s>>>(
                out_b, wbh + (size_t)(1 + i) * 65536, wbl + (size_t)(1 + i) * 65536,
                vp_b + (size_t)i * Cn, val_b, nullptr, nullptr, nullptr, nullptr,
                nullptr, HWn);
            wgemm<96, 1, false, 1><<<MBb, 512, wg_smem(96), s>>>(
                out_b, owh + (size_t)i * 96 * 256, owl + (size_t)i * 96 * 256,
                obias + (size_t)i * 96, offb_b, awb_b, pos, nullptr, nullptr,
                nullptr, HWn);
            sample_kernel<<<HWn, 256, 0, s>>>(val_b, offb_b, awb_b, attn_b);
            wgemm<256, 0, false, 2><<<MBb, 512, wg_smem(256), s>>>(
                attn_b, wbh + (size_t)(4 + i) * 65536, wbl + (size_t)(4 + i) * 65536,
                op_b + (size_t)i * Cn, nullptr, nullptr, nullptr, out_b,
                ln1_g + (size_t)i * Cn, ln1_b + (size_t)i * Cn, HWn);
            // last layer: fused final transpose straight to d_out
            float* Tdst = (i == NLAYERS - 1)
                        ? out_final + (size_t)b * Cn * HWn : nullptr;
            wgemm_ffn<<<MBb, 512, FFN_SMEM, s>>>(
                out_b,
                wbh + (size_t)(7 + i) * 65536, wbl + (size_t)(7 + i) * 65536,
                l1_b + (size_t)i * Cn,
                wbh + (size_t)(10 + i) * 65536, wbl + (size_t)(10 + i) * 65536,
                l2_b + (size_t)i * Cn,
                ln2_g + (size_t)i * Cn, ln2_b + (size_t)i * Cn, HWn, Tdst);
        }
    }

    // join batch-1 stream back to origin before capture ends
    cudaEventRecord(g_evT1, g_s2);
    cudaStreamWaitEvent((cudaStream_t)0, g_evT1, 0);
}

// round 17
// speedup vs baseline: 1.4935x; 1.4935x over previous
#include <cuda_runtime.h>
#include <cuda_bf16.h>
#include <mma.h>
#include <cstdint>
#include <math.h>

using namespace nvcuda;

// Problem constants
#define BSn   2
#define Cn    256
#define Hn    200
#define Wn    200
#define HWn   (Hn * Wn)          // 40000
#define Mn    (BSn * HWn)        // 80000
#define MnPad (Mn + 128)         // pad so last-tile overreads stay in bounds
#define NLAYERS 3
#define HDn   32

// -------- scratch (static device arrays; no allocation allowed) ----------
__device__ float g_out [ (size_t)MnPad * Cn ];
__device__ float g_pos [ (size_t)HWn * Cn ];
__device__ float g_val [ (size_t)MnPad * Cn ];
__device__ float g_attn[ (size_t)MnPad * Cn ];
__device__ float g_off [ (size_t)MnPad * 64 ];
__device__ float g_aw  [ (size_t)MnPad * 32 ];

// pre-split bf16 weights: [0]=proj, [1..3]=vp, [4..6]=op, [7..9]=l1, [10..12]=l2
__device__ __nv_bfloat16 g_wb_hi[13][65536];
__device__ __nv_bfloat16 g_wb_lo[13][65536];
__device__ __nv_bfloat16 g_ow_hi[3][96 * 256];
__device__ __nv_bfloat16 g_ow_lo[3][96 * 256];
__device__ float g_obias[3][96];

// -------- streams + events (created at load time, before harness) ---------
static cudaStream_t g_s2, g_s3;
static cudaEvent_t g_evFork, g_evPrep, g_evT1;
static struct StreamInit {
    StreamInit() {
        cudaStreamCreateWithFlags(&g_s2, cudaStreamNonBlocking);
        cudaStreamCreateWithFlags(&g_s3, cudaStreamNonBlocking);
        cudaEventCreateWithFlags(&g_evFork, cudaEventDisableTiming);
        cudaEventCreateWithFlags(&g_evPrep, cudaEventDisableTiming);
        cudaEventCreateWithFlags(&g_evT1, cudaEventDisableTiming);
    }
} g_stream_init;

// ======================= helpers ==========================================
__device__ __forceinline__ void split4(float4 v, uint32_t& h01, uint32_t& h23,
                                       uint32_t& l01, uint32_t& l23)
{
    asm("cvt.rn.bf16x2.f32 %0, %1, %2;" : "=r"(h01) : "f"(v.y), "f"(v.x));
    asm("cvt.rn.bf16x2.f32 %0, %1, %2;" : "=r"(h23) : "f"(v.w), "f"(v.z));
    float r0 = v.x - __uint_as_float(h01 << 16);
    float r1 = v.y - __uint_as_float(h01 & 0xFFFF0000u);
    float r2 = v.z - __uint_as_float(h23 << 16);
    float r3 = v.w - __uint_as_float(h23 & 0xFFFF0000u);
    asm("cvt.rn.bf16x2.f32 %0, %1, %2;" : "=r"(l01) : "f"(r1), "f"(r0));
    asm("cvt.rn.bf16x2.f32 %0, %1, %2;" : "=r"(l23) : "f"(r3), "f"(r2));
}

__device__ __forceinline__ void sts_v2(uint32_t addr, uint32_t a, uint32_t b) {
    asm volatile("st.shared.v2.b32 [%0], {%1,%2};" :: "r"(addr), "r"(a), "r"(b) : "memory");
}

__device__ __forceinline__ uint32_t smem_u32(const void* p) {
    uint32_t a;
    asm("{ .reg .u64 t; cvta.to.shared.u64 t, %1; cvt.u32.u64 %0, t; }"
        : "=r"(a) : "l"(p));
    return a;
}

__device__ __forceinline__ void cp_async16(uint32_t dst, const void* src) {
    asm volatile("cp.async.cg.shared.global [%0], [%1], 16;"
                 :: "r"(dst), "l"(src) : "memory");
}
__device__ __forceinline__ void cp_commit() {
    asm volatile("cp.async.commit_group;" ::: "memory");
}
__device__ __forceinline__ void cp_wait_all() {
    asm volatile("cp.async.wait_group 0;" ::: "memory");
}
__device__ __forceinline__ void cp_wait1() {
    asm volatile("cp.async.wait_group 1;" ::: "memory");
}

// ======================= weight prep kernels ===============================
__global__ void conv_w_kernel(const float* __restrict__ src,
                              __nv_bfloat16* __restrict__ hi,
                              __nv_bfloat16* __restrict__ lo, int n)
{
    int i = (blockIdx.x * 256 + threadIdx.x) * 4;
    if (i >= n) return;
    float4 v = *(const float4*)(src + i);
    uint32_t h01, h23, l01, l23;
    split4(v, h01, h23, l01, l23);
    *(uint2*)((char*)hi + (size_t)i * 2) = make_uint2(h01, h23);
    *(uint2*)((char*)lo + (size_t)i * 2) = make_uint2(l01, l23);
}

__global__ void conv_ow_kernel(const float* __restrict__ off_w,
                               const float* __restrict__ aw_w)
{
    int idx = (blockIdx.x * 256 + threadIdx.x) * 4;
    if (idx >= 3 * 96 * 256) return;
    int layer = idx / (96 * 256);
    int rem = idx - layer * 96 * 256;
    int r = rem >> 8, c = rem & 255;
    const float* src = (r < 64)
        ? off_w + ((size_t)layer * 64 + r) * 256 + c
        : aw_w + ((size_t)layer * 32 + (r - 64)) * 256 + c;
    float4 v = *(const float4*)src;
    uint32_t h01, h23, l01, l23;
    split4(v, h01, h23, l01, l23);
    *(uint2*)((char*)&g_ow_hi[layer][rem]) = make_uint2(h01, h23);
    *(uint2*)((char*)&g_ow_lo[layer][rem]) = make_uint2(l01, l23);
}

__global__ void conv_obias_kernel(const float* __restrict__ off_b,
                                  const float* __restrict__ aw_b)
{
    int idx = threadIdx.x;
    if (idx >= 3 * 96) return;
    int layer = idx / 96, r = idx % 96;
    g_obias[layer][r] = (r < 64) ? off_b[layer * 64 + r] : aw_b[layer * 32 + (r - 64)];
}

// ======================= WMMA bf16x3 GEMM (512 threads, KCH=32) ============
// CTA tile 128 x BN; per-batch M with mEnd write guard (last tile partial).
// EPI: 0 = bias(+relu) -> C ; 1 = bias, split 64/32 -> C,C2 ;
//      2 = bias + residual + LayerNorm -> R (in place)
template<int BN, bool ADD_POS, bool RELU, int EPI>
__global__ __launch_bounds__(512)
void wgemm(const float* __restrict__ A,
           const __nv_bfloat16* __restrict__ Bh,
           const __nv_bfloat16* __restrict__ Bl,
           const float* __restrict__ bias, float* __restrict__ C,
           float* __restrict__ C2, const float* __restrict__ pos,
           float* __restrict__ R, const float* __restrict__ lng,
           const float* __restrict__ lnb, int mEnd)
{
    constexpr int K = 256, KCH = 32, NCHUNK = K / KCH;
    constexpr int BM = 128;
    constexpr int WARPS_N = (BN == 256) ? 4 : 2;
    constexpr int WARPS_M = 16 / WARPS_N;
    constexpr int MF = (BM / WARPS_M) / 16;
    constexpr int NF = (BN / WARPS_N) / 16;
    constexpr int STR = 40;
    constexpr int ABYTES = BM * STR * 2;
    constexpr int BBYTES = BN * STR * 2;
    constexpr int STAGE = 2 * ABYTES + 2 * BBYTES;

    extern __shared__ char smem[];
    uint32_t sbase = smem_u32(smem);
    float* cs = (float*)smem;

    int tid = threadIdx.x;
    int w = tid >> 5;
    int lane = tid & 31;
    int wm0 = (w / WARPS_N) * (BM / WARPS_M);
    int wn0 = (w % WARPS_N) * (BN / WARPS_N);
    int m0 = blockIdx.x * BM;

    wmma::fragment<wmma::accumulator, 16, 16, 16, float> acc[MF][NF];
#pragma unroll
    for (int i = 0; i < MF; i++)
#pragma unroll
        for (int j = 0; j < NF; j++) wmma::fill_fragment(acc[i][j], 0.f);

    float4 areg[2];
    auto load_A = [&](int c) {
        int k0 = c * KCH;
#pragma unroll
        for (int it = 0; it < 2; it++) {
            int idx = tid + it * 512;
            int row = idx >> 3;
            int c4 = (idx & 7) << 2;
            int m = m0 + row;
            float4 v = *(const float4*)(A + (size_t)m * K + k0 + c4);
            if (ADD_POS) {
                int pm = m - (m >= HWn ? HWn : 0);
                float4 p = *(const float4*)(pos + (size_t)pm * K + k0 + c4);
                v.x += p.x; v.y += p.y; v.z += p.z; v.w += p.w;
            }
            areg[it] = v;
        }
    };
    auto sts_A = [&](int c) {
        uint32_t a_hi = sbase + (c & 1) * STAGE;
        uint32_t a_lo = a_hi + ABYTES;
#pragma unroll
        for (int it = 0; it < 2; it++) {
            int idx = tid + it * 512;
            int row = idx >> 3;
            int c4 = (idx & 7) << 2;
            uint32_t h01, h23, l01, l23;
            split4(areg[it], h01, h23, l01, l23);
            uint32_t off = (uint32_t)(row * STR + c4) * 2;
            sts_v2(a_hi + off, h01, h23);
            sts_v2(a_lo + off, l01, l23);
        }
    };
    auto cp_B = [&](int c) {
        int k0 = c * KCH;
        uint32_t b_hi = sbase + (c & 1) * STAGE + 2 * ABYTES;
        constexpr int OPS = BN * 4 * 2;
#pragma unroll
        for (int it = 0; it < (OPS + 511) / 512; it++) {
            int idx = tid + it * 512;
            if (OPS % 512 && idx >= OPS) break;
            int half = idx / (BN * 4);
            int rem = idx - half * (BN * 4);
            int r = rem >> 2, ch = rem & 3;
            const __nv_bfloat16* src =
                (half ? Bl : Bh) + (size_t)r * K + k0 + ch * 8;
            cp_async16(b_hi + half * BBYTES + (uint32_t)(r * STR + ch * 8) * 2, src);
        }
        cp_commit();
    };

    load_A(0);
    sts_A(0);
    cp_B(0);

    for (int c = 0; c < NCHUNK; c++) {
        cp_wait_all();
        __syncthreads();
        if (c + 1 < NCHUNK) { cp_B(c + 1); load_A(c + 1); }

        const __nv_bfloat16* a_hi =
            (const __nv_bfloat16*)(smem + (c & 1) * STAGE);
        const __nv_bfloat16* b_base =
            (const __nv_bfloat16*)(smem + (c & 1) * STAGE + 2 * ABYTES);
#pragma unroll
        for (int ks = 0; ks < 2; ks++) {
            wmma::fragment<wmma::matrix_a, 16, 16, 16, __nv_bfloat16, wmma::row_major> ah[MF], al[MF];
#pragma unroll
            for (int i = 0; i < MF; i++) {
                const __nv_bfloat16* pa = a_hi + (wm0 + i * 16) * STR + ks * 16;
                wmma::load_matrix_sync(ah[i], pa, STR);
                wmma::load_matrix_sync(al[i], pa + BM * STR, STR);
            }
#pragma unroll
            for (int j = 0; j < NF; j++) {
                wmma::fragment<wmma::matrix_b, 16, 16, 16, __nv_bfloat16, wmma::col_major> bh, bl;
                const __nv_bfloat16* pb = b_base + (wn0 + j * 16) * STR + ks * 16;
                wmma::load_matrix_sync(bh, pb, STR);
                wmma::load_matrix_sync(bl, pb + BN * STR, STR);
#pragma unroll
                for (int i = 0; i < MF; i++) {
                    wmma::mma_sync(acc[i][j], ah[i], bh, acc[i][j]);
                    wmma::mma_sync(acc[i][j], ah[i], bl, acc[i][j]);
                    wmma::mma_sync(acc[i][j], al[i], bh, acc[i][j]);
                }
            }
        }
        if (c + 1 < NCHUNK) sts_A(c + 1);
    }

    __syncthreads();
#pragma unroll
    for (int i = 0; i < MF; i++)
#pragma unroll
        for (int j = 0; j < NF; j++)
            wmma::store_matrix_sync(cs + (wm0 + i * 16) * (BN + 4) + wn0 + j * 16,
                                    acc[i][j], BN + 4, wmma::mem_row_major);
    __syncthreads();

    if (EPI == 2) {
#pragma unroll
        for (int r8 = 0; r8 < BM / 16; r8++) {
            int row = w * (BM / 16) + r8;
            int m = m0 + row;
            if (m >= mEnd) continue;
            float* rp = R + (size_t)m * 256 + lane * 8;
            const float* csr = cs + row * (BN + 4) + lane * 8;
            float v[8];
            float4 c0 = *(const float4*)(csr);
            float4 c1 = *(const float4*)(csr + 4);
            float4 q0 = *(const float4*)(rp);
            float4 q1 = *(const float4*)(rp + 4);
            float4 b0 = *(const float4*)(bias + lane * 8);
            float4 b1 = *(const float4*)(bias + lane * 8 + 4);
            v[0] = c0.x + q0.x + b0.x; v[1] = c0.y + q0.y + b0.y;
            v[2] = c0.z + q0.z + b0.z; v[3] = c0.w + q0.w + b0.w;
            v[4] = c1.x + q1.x + b1.x; v[5] = c1.y + q1.y + b1.y;
            v[6] = c1.z + q1.z + b1.z; v[7] = c1.w + q1.w + b1.w;
            float s = 0.f;
#pragma unroll
            for (int i = 0; i < 8; i++) s += v[i];
#pragma unroll
            for (int o = 16; o > 0; o >>= 1) s += __shfl_xor_sync(0xffffffffu, s, o);
            float mean = s * (1.f / 256.f);
            float s2 = 0.f;
#pragma unroll
            for (int i = 0; i < 8; i++) { float d = v[i] - mean; s2 += d * d; }
#pragma unroll
            for (int o = 16; o > 0; o >>= 1) s2 += __shfl_xor_sync(0xffffffffu, s2, o);
            float inv = rsqrtf(s2 * (1.f / 256.f) + 1e-5f);
            float4 g0 = *(const float4*)(lng + lane * 8);
            float4 g1 = *(const float4*)(lng + lane * 8 + 4);
            float4 t0 = *(const float4*)(lnb + lane * 8);
            float4 t1 = *(const float4*)(lnb + lane * 8 + 4);
            float4 o0, o1;
            o0.x = (v[0] - mean) * inv * g0.x + t0.x;
            o0.y = (v[1] - mean) * inv * g0.y + t0.y;
            o0.z = (v[2] - mean) * inv * g0.z + t0.z;
            o0.w = (v[3] - mean) * inv * g0.w + t0.w;
            o1.x = (v[4] - mean) * inv * g1.x + t1.x;
            o1.y = (v[5] - mean) * inv * g1.y + t1.y;
            o1.z = (v[6] - mean) * inv * g1.z + t1.z;
            o1.w = (v[7] - mean) * inv * g1.w + t1.w;
            *(float4*)(rp) = o0;
            *(float4*)(rp + 4) = o1;
        }
    } else {
        constexpr int ITERS = (BM * BN / 4) / 512;
#pragma unroll
        for (int it = 0; it < ITERS; it++) {
            int idx = tid + it * 512;
            int row = idx / (BN / 4);
            int c4  = (idx % (BN / 4)) * 4;
            int m = m0 + row;
            if (m >= mEnd) continue;
            float4 o = *(const float4*)(cs + row * (BN + 4) + c4);
            o.x += __ldg(bias + c4 + 0);
            o.y += __ldg(bias + c4 + 1);
            o.z += __ldg(bias + c4 + 2);
            o.w += __ldg(bias + c4 + 3);
            if (RELU) {
                o.x = fmaxf(o.x, 0.f); o.y = fmaxf(o.y, 0.f);
                o.z = fmaxf(o.z, 0.f); o.w = fmaxf(o.w, 0.f);
            }
            if (EPI == 1) {
                if (c4 < 64) *(float4*)(C  + (size_t)m * 64 + c4)        = o;
                else         *(float4*)(C2 + (size_t)m * 32 + (c4 - 64)) = o;
            } else {
                *(float4*)(C + (size_t)m * BN + c4) = o;
            }
        }
    }
}

constexpr int wg_smem(int bn) {
    int stage = (2 * 128 + 2 * bn) * 40 * 2;
    int ab = 2 * stage;
    int cb = 128 * (bn + 4) * 4;
    return ab > cb ? ab : cb;
}

// ======================= fused FFN kernel (KCH=32) =========================
// out = LN(out + relu(out@l1^T + b1) @ l2^T + b2)
// If T != nullptr: write LN result TRANSPOSED to T[c][m] (fused final transpose).
__global__ __launch_bounds__(512)
void wgemm_ffn(float* __restrict__ A,
               const __nv_bfloat16* __restrict__ B1h, const __nv_bfloat16* __restrict__ B1l,
               const float* __restrict__ b1,
               const __nv_bfloat16* __restrict__ B2h, const __nv_bfloat16* __restrict__ B2l,
               const float* __restrict__ b2,
               const float* __restrict__ lng, const float* __restrict__ lnb,
               int mEnd, float* __restrict__ T)
{
    constexpr int K = 256, KCH = 32, NCHUNK = 8, BM = 128, BN = 256;
    constexpr int WARPS_N = 4, MF = 2, NF = 4;
    constexpr int STR = 40;
    constexpr int ABYTES = BM * STR * 2;
    constexpr int BBYTES = BN * STR * 2;
    constexpr int STAGE = 2 * ABYTES + 2 * BBYTES;
    constexpr int STR2 = 264;
    constexpr int A2_SPLIT = BM * STR2 * 2;
    constexpr int CSH_OFF = 2 * A2_SPLIT;
    constexpr int B2_STAGE = 2 * BBYTES;

    extern __shared__ char smem[];
    uint32_t sbase = smem_u32(smem);
    float* cs = (float*)smem;
    float* csh = (float*)(smem + CSH_OFF);

    int tid = threadIdx.x;
    int w = tid >> 5;
    int lane = tid & 31;
    int wm0 = (w / WARPS_N) * 32;
    int wn0 = (w % WARPS_N) * 64;
    int m0 = blockIdx.x * BM;

    wmma::fragment<wmma::accumulator, 16, 16, 16, float> acc[MF][NF];
#pragma unroll
    for (int i = 0; i < MF; i++)
#pragma unroll
        for (int j = 0; j < NF; j++) wmma::fill_fragment(acc[i][j], 0.f);

    float4 areg[2];
    auto load_A = [&](int c) {
        int k0 = c * KCH;
#pragma unroll
        for (int it = 0; it < 2; it++) {
            int idx = tid + it * 512;
            int row = idx >> 3;
            int c4 = (idx & 7) << 2;
            areg[it] = *(const float4*)(A + (size_t)(m0 + row) * K + k0 + c4);
        }
    };
    auto sts_A = [&](int c) {
        uint32_t a_hi = sbase + (c & 1) * STAGE;
        uint32_t a_lo = a_hi + ABYTES;
#pragma unroll
        for (int it = 0; it < 2; it++) {
            int idx = tid + it * 512;
            int row = idx >> 3;
            int c4 = (idx & 7) << 2;
            uint32_t h01, h23, l01, l23;
            split4(areg[it], h01, h23, l01, l23);
            uint32_t off = (uint32_t)(row * STR + c4) * 2;
            sts_v2(a_hi + off, h01, h23);
            sts_v2(a_lo + off, l01, l23);
        }
    };
    auto cp_B1 = [&](int c) {
        int k0 = c * KCH;
        uint32_t b_hi = sbase + (c & 1) * STAGE + 2 * ABYTES;
#pragma unroll
        for (int it = 0; it < 4; it++) {
            int idx = tid + it * 512;
            int half = idx >> 10;
            int rem = idx & 1023;
            int r = rem >> 2, ch = rem & 3;
            const __nv_bfloat16* src =
                (half ? B1l : B1h) + (size_t)r * K + k0 + ch * 8;
            cp_async16(b_hi + half * BBYTES + (uint32_t)(r * STR + ch * 8) * 2, src);
        }
        cp_commit();
    };

    load_A(0);
    sts_A(0);
    cp_B1(0);

    for (int c = 0; c < NCHUNK; c++) {
        cp_wait_all();
        __syncthreads();
        if (c + 1 < NCHUNK) { cp_B1(c + 1); load_A(c + 1); }

        const __nv_bfloat16* a_hi = (const __nv_bfloat16*)(smem + (c & 1) * STAGE);
        const __nv_bfloat16* b_base = (const __nv_bfloat16*)(smem + (c & 1) * STAGE + 2 * ABYTES);
#pragma unroll
        for (int ks = 0; ks < 2; ks++) {
            wmma::fragment<wmma::matrix_a, 16, 16, 16, __nv_bfloat16, wmma::row_major> ah[MF], al[MF];
#pragma unroll
            for (int i = 0; i < MF; i++) {
                const __nv_bfloat16* pa = a_hi + (wm0 + i * 16) * STR + ks * 16;
                wmma::load_matrix_sync(ah[i], pa, STR);
                wmma::load_matrix_sync(al[i], pa + BM * STR, STR);
            }
#pragma unroll
            for (int j = 0; j < NF; j++) {
                wmma::fragment<wmma::matrix_b, 16, 16, 16, __nv_bfloat16, wmma::col_major> bh, bl;
                const __nv_bfloat16* pb = b_base + (wn0 + j * 16) * STR + ks * 16;
                wmma::load_matrix_sync(bh, pb, STR);
                wmma::load_matrix_sync(bl, pb + BN * STR, STR);
#pragma unroll
                for (int i = 0; i < MF; i++) {
                    wmma::mma_sync(acc[i][j], ah[i], bh, acc[i][j]);
                    wmma::mma_sync(acc[i][j], ah[i], bl, acc[i][j]);
                    wmma::mma_sync(acc[i][j], al[i], bh, acc[i][j]);
                }
            }
        }
        if (c + 1 < NCHUNK) sts_A(c + 1);
    }

    // convert ffn1 -> bf16 hi/lo tile in smem
#pragma unroll
    for (int half = 0; half < 2; half++) {
        __syncthreads();
        if ((wn0 < 128) == (half == 0)) {
            int lwn = wn0 - half * 128;
#pragma unroll
            for (int i = 0; i < MF; i++)
#pragma unroll
                for (int j = 0; j < NF; j++)
                    wmma::store_matrix_sync(csh + (wm0 + i * 16) * 132 + lwn + j * 16,
                                            acc[i][j], 132, wmma::mem_row_major);
        }
        __syncthreads();
#pragma unroll
        for (int it = 0; it < 8; it++) {
            int idx = tid + it * 512;
            int row = idx >> 5;
            int lc4 = (idx & 31) << 2;
            int gcol = half * 128 + lc4;
            float4 o = *(const float4*)(csh + row * 132 + lc4);
            o.x = fmaxf(o.x + __ldg(b1 + gcol + 0), 0.f);
            o.y = fmaxf(o.y + __ldg(b1 + gcol + 1), 0.f);
            o.z = fmaxf(o.z + __ldg(b1 + gcol + 2), 0.f);
            o.w = fmaxf(o.w + __ldg(b1 + gcol + 3), 0.f);
            uint32_t h01, h23, l01, l23;
            split4(o, h01, h23, l01, l23);
            uint32_t off = (uint32_t)(row * STR2 + gcol) * 2;
            sts_v2(sbase + off, h01, h23);
            sts_v2(sbase + A2_SPLIT + off, l01, l23);
        }
    }
    __syncthreads();

    // GEMM2: ffn1 @ l2^T
#pragma unroll
    for (int i = 0; i < MF; i++)
#pragma unroll
        for (int j = 0; j < NF; j++) wmma::fill_fragment(acc[i][j], 0.f);

    auto cp_B2 = [&](int c) {
        int k0 = c * KCH;
        uint32_t st = sbase + CSH_OFF + (c & 1) * B2_STAGE;
#pragma unroll
        for (int it = 0; it < 4; it++) {
            int idx = tid + it * 512;
            int half = idx >> 10;
            int rem = idx & 1023;
            int r = rem >> 2, ch = rem & 3;
            const __nv_bfloat16* src =
                (half ? B2l : B2h) + (size_t)r * K + k0 + ch * 8;
            cp_async16(st + half * BBYTES + (uint32_t)(r * STR + ch * 8) * 2, src);
        }
        cp_commit();
    };

    cp_B2(0);
    cp_B2(1);

    const __nv_bfloat16* a2h = (const __nv_bfloat16*)smem;
    for (int c = 0; c < NCHUNK; c++) {
        if (c < NCHUNK - 2) { cp_wait1(); } else { cp_wait_all(); }
        __syncthreads();

        const __nv_bfloat16* b_base =
            (const __nv_bfloat16*)(smem + CSH_OFF + (c & 1) * B2_STAGE);
#pragma unroll
        for (int ks = 0; ks < 2; ks++) {
            int kc = c * KCH + ks * 16;
            wmma::fragment<wmma::matrix_a, 16, 16, 16, __nv_bfloat16, wmma::row_major> ah[MF], al[MF];
#pragma unroll
            for (int i = 0; i < MF; i++) {
                const __nv_bfloat16* pa = a2h + (wm0 + i * 16) * STR2 + kc;
                wmma::load_matrix_sync(ah[i], pa, STR2);
                wmma::load_matrix_sync(al[i], pa + BM * STR2, STR2);
            }
#pragma unroll
            for (int j = 0; j < NF; j++) {
                wmma::fragment<wmma::matrix_b, 16, 16, 16, __nv_bfloat16, wmma::col_major> bh, bl;
                const __nv_bfloat16* pb = b_base + (wn0 + j * 16) * STR + ks * 16;
                wmma::load_matrix_sync(bh, pb, STR);
                wmma::load_matrix_sync(bl, pb + BN * STR, STR);
#pragma unroll
                for (int i = 0; i < MF; i++) {
                    wmma::mma_sync(acc[i][j], ah[i], bh, acc[i][j]);
                    wmma::mma_sync(acc[i][j], ah[i], bl, acc[i][j]);
                    wmma::mma_sync(acc[i][j], al[i], bh, acc[i][j]);
                }
            }
        }
        __syncthreads();
        if (c + 2 < NCHUNK) cp_B2(c + 2);
    }

    // LN epilogue
    __syncthreads();
#pragma unroll
    for (int i = 0; i < MF; i++)
#pragma unroll
        for (int j = 0; j < NF; j++)
            wmma::store_matrix_sync(cs + (wm0 + i * 16) * (BN + 4) + wn0 + j * 16,
                                    acc[i][j], BN + 4, wmma::mem_row_major);
    __syncthreads();

#pragma unroll
    for (int r8 = 0; r8 < BM / 16; r8++) {
        int row = w * (BM / 16) + r8;
        int m = m0 + row;
        if (m >= mEnd) continue;
        float* rp = A + (size_t)m * 256 + lane * 8;
        float* csr = cs + row * (BN + 4) + lane * 8;
        float v[8];
        float4 c0 = *(const float4*)(csr);
        float4 c1 = *(const float4*)(csr + 4);
        float4 q0 = *(const float4*)(rp);
        float4 q1 = *(const float4*)(rp + 4);
        float4 b0 = *(const float4*)(b2 + lane * 8);
        float4 b1v = *(const float4*)(b2 + lane * 8 + 4);
        v[0] = c0.x + q0.x + b0.x; v[1] = c0.y + q0.y + b0.y;
        v[2] = c0.z + q0.z + b0.z; v[3] = c0.w + q0.w + b0.w;
        v[4] = c1.x + q1.x + b1v.x; v[5] = c1.y + q1.y + b1v.y;
        v[6] = c1.z + q1.z + b1v.z; v[7] = c1.w + q1.w + b1v.w;
        float s = 0.f;
#pragma unroll
        for (int i = 0; i < 8; i++) s += v[i];
#pragma unroll
        for (int o = 16; o > 0; o >>= 1) s += __shfl_xor_sync(0xffffffffu, s, o);
        float mean = s * (1.f / 256.f);
        float s2 = 0.f;
#pragma unroll
        for (int i = 0; i < 8; i++) { float d = v[i] - mean; s2 += d * d; }
#pragma unroll
        for (int o = 16; o > 0; o >>= 1) s2 += __shfl_xor_sync(0xffffffffu, s2, o);
        float inv = rsqrtf(s2 * (1.f / 256.f) + 1e-5f);
        float4 g0 = *(const float4*)(lng + lane * 8);
        float4 g1 = *(const float4*)(lng + lane * 8 + 4);
        float4 t0 = *(const float4*)(lnb + lane * 8);
        float4 t1 = *(const float4*)(lnb + lane * 8 + 4);
        float4 o0, o1;
        o0.x = (v[0] - mean) * inv * g0.x + t0.x;
        o0.y = (v[1] - mean) * inv * g0.y + t0.y;
        o0.z = (v[2] - mean) * inv * g0.z + t0.z;
        o0.w = (v[3] - mean) * inv * g0.w + t0.w;
        o1.x = (v[4] - mean) * inv * g1.x + t1.x;
        o1.y = (v[5] - mean) * inv * g1.y + t1.y;
        o1.z = (v[6] - mean) * inv * g1.z + t1.z;
        o1.w = (v[7] - mean) * inv * g1.w + t1.w;
        if (T) {
            *(float4*)(csr) = o0;
            *(float4*)(csr + 4) = o1;
        } else {
            *(float4*)(rp) = o0;
            *(float4*)(rp + 4) = o1;
        }
    }

    if (T) {
        __syncthreads();
#pragma unroll
        for (int it = 0; it < 16; it++) {
            int idx = tid + it * 512;
            int c = idx >> 5;
            int rq = idx & 31;
            int m = m0 + rq * 4;
            if (m < mEnd) {
                float4 o;
                o.x = cs[(rq * 4 + 0) * (BN + 4) + c];
                o.y = cs[(rq * 4 + 1) * (BN + 4) + c];
                o.z = cs[(rq * 4 + 2) * (BN + 4) + c];
                o.w = cs[(rq * 4 + 3) * (BN + 4) + c];
                *(float4*)(T + (size_t)c * HWn + m) = o;
            }
        }
    }
}

constexpr int FFN_SMEM = 2 * (128 * 264 * 2) + 2 * (2 * 256 * 40 * 2);

// ======================= 32x32 tiled transpose (single batch) ==============
__global__ void transpose_kernel(const float* __restrict__ src,
                                 float* __restrict__ dst, int P, int Q)
{
    __shared__ float tile[32][33];
    int q0 = blockIdx.x * 32, p0 = blockIdx.y * 32;
    int tx = threadIdx.x, ty = threadIdx.y;
#pragma unroll
    for (int i = 0; i < 32; i += 8) {
        int p = p0 + ty + i, q = q0 + tx;
        if (p < P && q < Q) tile[ty + i][tx] = src[(size_t)p * Q + q];
    }
    __syncthreads();
#pragma unroll
    for (int i = 0; i < 32; i += 8) {
        int q = q0 + ty + i, p = p0 + tx;
        if (p < P && q < Q) dst[(size_t)q * P + p] = tile[tx][ty + i];
    }
}

// ======================= sine positional encoding ==========================
__global__ void pos_kernel(float* __restrict__ pos)
{
    int q = blockIdx.x;
    int c = threadIdx.x;
    int row = q / Wn, col = q % Wn;
    int cc = c;
    float v;
    if (cc < 128) { v = (float)(row + 1); }
    else          { v = (float)(col + 1); cc -= 128; }
    int j = cc >> 1;
    float t = powf(10000.f, (float)(2 * j) * (1.f / 128.f));
    float arg = v / t;
    pos[(size_t)q * Cn + c] = (cc & 1) ? cosf(arg) : sinf(arg);
}

// ======================= deformable sampling (single batch) ================
__global__ __launch_bounds__(256)
void sample_kernel(const float* __restrict__ value, const float* __restrict__ off,
                   const float* __restrict__ aw, float* __restrict__ attn)
{
    int q = blockIdx.x;
    int h = threadIdx.x >> 5;
    int lane = threadIdx.x & 31;
    size_t base = (size_t)q;

    const float* awp = aw + base * 32 + h * 4;
    float a0 = awp[0], a1 = awp[1], a2 = awp[2], a3 = awp[3];
    float mx = fmaxf(fmaxf(a0, a1), fmaxf(a2, a3));
    float e0 = expf(a0 - mx), e1 = expf(a1 - mx), e2 = expf(a2 - mx), e3 = expf(a3 - mx);
    float inv = 1.f / (e0 + e1 + e2 + e3);
    float wp[4] = {e0 * inv, e1 * inv, e2 * inv, e3 * inv};

    const float* offp = off + base * 64 + h * 8;
    int col = q % Wn, row = q / Wn;
    const float* vb = value + h * HDn + lane;

    float acc = 0.f;
#pragma unroll
    for (int p = 0; p < 4; p++) {
        float x = (float)col + offp[p * 2 + 0];
        float y = (float)row + offp[p * 2 + 1];
        float xf = floorf(x), yf = floorf(y);
        int x0 = (int)xf, y0 = (int)yf;
        float wx = x - xf, wy = y - yf;
        float w00 = (1.f - wx) * (1.f - wy), w10 = wx * (1.f - wy);
        float w01 = (1.f - wx) * wy,         w11 = wx * wy;
        float s = 0.f;
        if ((unsigned)x0 < (unsigned)Wn && (unsigned)y0 < (unsigned)Hn)
            s += w00 * vb[(size_t)(y0 * Wn + x0) * Cn];
        if ((unsigned)(x0 + 1) < (unsigned)Wn && (unsigned)y0 < (unsigned)Hn)
            s += w10 * vb[(size_t)(y0 * Wn + x0 + 1) * Cn];
        if ((unsigned)x0 < (unsigned)Wn && (unsigned)(y0 + 1) < (unsigned)Hn)
            s += w01 * vb[(size_t)((y0 + 1) * Wn + x0) * Cn];
        if ((unsigned)(x0 + 1) < (unsigned)Wn && (unsigned)(y0 + 1) < (unsigned)Hn)
            s += w11 * vb[(size_t)((y0 + 1) * Wn + x0 + 1) * Cn];
        acc += wp[p] * s;
    }
    attn[base * Cn + h * HDn + lane] = acc;
}

// ======================= launch ===========================================
extern "C" void kernel_launch(void* const* d_in, const int* in_sizes, int n_in,
                              void* d_out, int out_size)
{
    const float* bev      = (const float*)d_in[0];
    const float* proj_q_w = (const float*)d_in[1];
    const float* proj_q_b = (const float*)d_in[2];
    const float* off_w    = (const float*)d_in[3];
    const float* off_b    = (const float*)d_in[4];
    const float* aw_w     = (const float*)d_in[5];
    const float* aw_b     = (const float*)d_in[6];
    const float* vp_w     = (const float*)d_in[7];
    const float* vp_b     = (const float*)d_in[8];
    const float* op_w     = (const float*)d_in[9];
    const float* op_b     = (const float*)d_in[10];
    const float* ln1_g    = (const float*)d_in[11];
    const float* ln1_b    = (const float*)d_in[12];
    const float* l1_w     = (const float*)d_in[13];
    const float* l1_b     = (const float*)d_in[14];
    const float* l2_w     = (const float*)d_in[15];
    const float* l2_b     = (const float*)d_in[16];
    const float* ln2_g    = (const float*)d_in[17];
    const float* ln2_b    = (const float*)d_in[18];
    float* out_final      = (float*)d_out;

    float *out, *pos, *val, *attn, *offb, *awb, *obias;
    __nv_bfloat16 *wbh, *wbl, *owh, *owl;
    cudaGetSymbolAddress((void**)&out,  g_out);
    cudaGetSymbolAddress((void**)&pos,  g_pos);
    cudaGetSymbolAddress((void**)&val,  g_val);
    cudaGetSymbolAddress((void**)&attn, g_attn);
    cudaGetSymbolAddress((void**)&offb, g_off);
    cudaGetSymbolAddress((void**)&awb,  g_aw);
    cudaGetSymbolAddress((void**)&wbh, g_wb_hi);
    cudaGetSymbolAddress((void**)&wbl, g_wb_lo);
    cudaGetSymbolAddress((void**)&owh, g_ow_hi);
    cudaGetSymbolAddress((void**)&owl, g_ow_lo);
    cudaGetSymbolAddress((void**)&obias, g_obias);

    cudaFuncSetAttribute((const void*)wgemm<256, false, false, 0>,
                         cudaFuncAttributeMaxDynamicSharedMemorySize, wg_smem(256));
    cudaFuncSetAttribute((const void*)wgemm<256, false, false, 2>,
                         cudaFuncAttributeMaxDynamicSharedMemorySize, wg_smem(256));
    cudaFuncSetAttribute((const void*)wgemm<96, true, false, 1>,
                         cudaFuncAttributeMaxDynamicSharedMemorySize, wg_smem(96));
    cudaFuncSetAttribute((const void*)wgemm_ffn,
                         cudaFuncAttributeMaxDynamicSharedMemorySize, FFN_SMEM);

    dim3 tblk(32, 8);
    const int MBb = (HWn + 127) / 128;     // 313 CTAs per batch

    cudaStream_t sb[2] = { (cudaStream_t)0, g_s2 };

    // ---- fork prep stream (all weight conversion + pos)
    cudaEventRecord(g_evFork, 0);
    cudaStreamWaitEvent(g_s3, g_evFork, 0);
    cudaStreamWaitEvent(g_s2, g_evFork, 0);
    conv_w_kernel<<<64, 256, 0, g_s3>>>(proj_q_w, wbh + 0 * 65536, wbl + 0 * 65536, 65536);
    conv_w_kernel<<<192, 256, 0, g_s3>>>(vp_w, wbh + 1 * 65536, wbl + 1 * 65536, 3 * 65536);
    conv_w_kernel<<<192, 256, 0, g_s3>>>(op_w, wbh + 4 * 65536, wbl + 4 * 65536, 3 * 65536);
    conv_w_kernel<<<192, 256, 0, g_s3>>>(l1_w, wbh + 7 * 65536, wbl + 7 * 65536, 3 * 65536);
    conv_w_kernel<<<192, 256, 0, g_s3>>>(l2_w, wbh + 10 * 65536, wbl + 10 * 65536, 3 * 65536);
    conv_ow_kernel<<<72, 256, 0, g_s3>>>(off_w, aw_w);
    conv_obias_kernel<<<1, 288, 0, g_s3>>>(off_b, aw_b);
    pos_kernel<<<HWn, 256, 0, g_s3>>>(pos);
    cudaEventRecord(g_evPrep, g_s3);

    // ---- per-batch transposes (independent of prep)
    {
        dim3 grid((HWn + 31) / 32, Cn / 32);
        transpose_kernel<<<grid, tblk, 0, sb[0]>>>(bev, attn, Cn, HWn);
        transpose_kernel<<<grid, tblk, 0, sb[1]>>>(bev + (size_t)Cn * HWn,
                                                   attn + (size_t)HWn * Cn, Cn, HWn);
    }
    cudaStreamWaitEvent(sb[0], g_evPrep, 0);
    cudaStreamWaitEvent(sb[1], g_evPrep, 0);

    // ---- per-batch chains on two streams
    for (int b = 0; b < BSn; b++) {
        cudaStream_t s = sb[b];
        size_t ro = (size_t)b * HWn;                 // row offset
        float* out_b  = out  + ro * Cn;
        float* val_b  = val  + ro * Cn;
        float* attn_b = attn + ro * Cn;
        float* offb_b = offb + ro * 64;
        float* awb_b  = awb  + ro * 32;

        // proj
        wgemm<256, false, false, 0><<<MBb, 512, wg_smem(256), s>>>(
            attn_b, wbh + 0 * 65536, wbl + 0 * 65536, proj_q_b, out_b,
            nullptr, nullptr, nullptr, nullptr, nullptr, HWn);

        for (int i = 0; i < NLAYERS; i++) {
            wgemm<256, false, false, 0><<<MBb, 512, wg_smem(256), s>>>(
                out_b, wbh + (size_t)(1 + i) * 65536, wbl + (size_t)(1 + i) * 65536,
                vp_b + (size_t)i * Cn, val_b, nullptr, nullptr, nullptr, nullptr,
                nullptr, HWn);
            wgemm<96, true, false, 1><<<MBb, 512, wg_smem(96), s>>>(
                out_b, owh + (size_t)i * 96 * 256, owl + (size_t)i * 96 * 256,
                obias + (size_t)i * 96, offb_b, awb_b, pos, nullptr, nullptr,
                nullptr, HWn);
            sample_kernel<<<HWn, 256, 0, s>>>(val_b, offb_b, awb_b, attn_b);
            wgemm<256, false, false, 2><<<MBb, 512, wg_smem(256), s>>>(
                attn_b, wbh + (size_t)(4 + i) * 65536, wbl + (size_t)(4 + i) * 65536,
                op_b + (size_t)i * Cn, nullptr, nullptr, nullptr, out_b,
                ln1_g + (size_t)i * Cn, ln1_b + (size_t)i * Cn, HWn);
            // last layer: fused final transpose straight to d_out
            float* Tdst = (i == NLAYERS - 1)
                        ? out_final + (size_t)b * Cn * HWn : nullptr;
            wgemm_ffn<<<MBb, 512, FFN_SMEM, s>>>(
                out_b,
                wbh + (size_t)(7 + i) * 65536, wbl + (size_t)(7 + i) * 65536,
                l1_b + (size_t)i * Cn,
                wbh + (size_t)(10 + i) * 65536, wbl + (size_t)(10 + i) * 65536,
                l2_b + (size_t)i * Cn,
                ln2_g + (size_t)i * Cn, ln2_b + (size_t)i * Cn, HWn, Tdst);
        }
    }

    // join batch-1 stream back to origin before capture ends
    cudaEventRecord(g_evT1, g_s2);
    cudaStreamWaitEvent((cudaStream_t)0, g_evT1, 0);
}